// round 13
// baseline (speedup 1.0000x reference)
#include <cuda_runtime.h>

// Shapes (fixed per reference): T=8, B=32, C=128, H=W=32
#define TT 8
#define BB 32
#define CC_ 128
#define HW 1024
#define IMG 256              // T*B images
#define PLANE (BB*CC_*HW)    // 4194304
#define TOT (TT*PLANE)       // 33554432

#define KMEM 16              // ensemble members (8 antithetic pairs)
#define SIGMA 5.0e-6f        // per-site conv-output noise std (ref sigma est.)

// Scratch (device globals: allocation-free per harness rules)
__device__ float  g_bufL1[TOT];    // exact L1 conv output (shared by members)
__device__ float  g_bufS[TOT];     // member spikes
__device__ float  g_bufC[TOT];     // member conv output (L2/L3)
__device__ double g_sums[CC_];
__device__ double g_sumsq[CC_];
__device__ float  g_meanA[2][CC_]; // slot 0: per-member scratch; slot 1: L1
__device__ float  g_rstdA[2][CC_];
__device__ float  g_feat[BB*CC_];  // sum of spike-probs over members

// ---- packed f32x2 helpers ----
__device__ __forceinline__ unsigned long long dup2(float v) {
    unsigned long long r; unsigned u = __float_as_uint(v);
    asm("mov.b64 %0, {%1, %1};" : "=l"(r) : "r"(u));
    return r;
}
__device__ __forceinline__ void fma2(unsigned long long& d,
                                     unsigned long long a, unsigned long long b) {
    asm("fma.rn.f32x2 %0, %1, %2, %0;" : "+l"(d) : "l"(a), "l"(b));
}
__device__ __forceinline__ unsigned long long add2(unsigned long long a,
                                                   unsigned long long b) {
    unsigned long long r;
    asm("add.rn.f32x2 %0, %1, %2;" : "=l"(r) : "l"(a), "l"(b));
    return r;
}
__device__ __forceinline__ unsigned long long mul2(unsigned long long a,
                                                   unsigned long long b) {
    unsigned long long r;
    asm("mul.rn.f32x2 %0, %1, %2;" : "=l"(r) : "l"(a), "l"(b));
    return r;
}
__device__ __forceinline__ float2 unp(unsigned long long v) {
    unsigned lo, hi;
    asm("mov.b64 {%0, %1}, %2;" : "=r"(lo), "=r"(hi) : "l"(v));
    return make_float2(__uint_as_float(lo), __uint_as_float(hi));
}

// ---- deterministic per-site Gaussian-ish noise (Irwin-Hall of 4 bytes) ----
__device__ __forceinline__ float gnoise(unsigned gid, unsigned seed) {
    unsigned h = gid ^ (seed * 0x9E3779B9u);
    h ^= h >> 16; h *= 0x7feb352du;
    h ^= h >> 15; h *= 0x846ca68bu;
    h ^= h >> 16;
    int s = (int)((h & 255u) + ((h >> 8) & 255u) + ((h >> 16) & 255u) +
                  ((h >> 24) & 255u)) - 510;
    return (float)s * (1.0f / 147.8f);   // ~unit variance, +-3.45 sigma
}

// ============================================================================
// EXACT direct conv 3x3 pad1 (compensated fp32; ~1e-7) — ensemble CENTER.
// Layer 1 only (runs once). Block: 1 image, 8 rows x 32 cols, 64 oc.
// ============================================================================
__global__ __launch_bounds__(256, 1)
void conv_x(const float* __restrict__ x, const float* __restrict__ w,
            float* __restrict__ y) {
    __shared__ __align__(16) float in_s[8][10][36];
    __shared__ __align__(16) float w_s[72][64];

    const int tid = threadIdx.x;
    const int img = blockIdx.y;
    const int hbase = ((blockIdx.x >> 1) & 3) * 8;
    const int co_base = (blockIdx.x & 1) * 64;
    const float* xb = x + (size_t)img * CC_ * HW;
    float* yb = y + ((size_t)img * CC_ + co_base) * HW;

    const int oc_g = (tid & 7) * 8;
    const int pg = tid >> 3;
    const int cb = (pg & 7) * 4;
    const int rp = pg >> 3;
    const unsigned long long M1 = dup2(-1.0f);

    unsigned long long hi[2][4][4], lo[2][4][4], ch[2][4][4];
    #pragma unroll
    for (int r = 0; r < 2; r++)
        #pragma unroll
        for (int p = 0; p < 4; p++)
            #pragma unroll
            for (int q = 0; q < 4; q++) { hi[r][p][q] = 0ull; lo[r][p][q] = 0ull; ch[r][p][q] = 0ull; }

    for (int ci0 = 0; ci0 < CC_; ci0 += 8) {
        for (int i = tid; i < 8 * 10 * 34; i += 256) {
            int cch = i / 340;
            int rem = i - cch * 340;
            int r = rem / 34;
            int col = rem - r * 34;
            int gr = hbase + r - 1;
            int gc = col - 1;
            float v = 0.f;
            if ((unsigned)gr < 32u && (unsigned)gc < 32u)
                v = xb[(ci0 + cch) * HW + gr * 32 + gc];
            in_s[cch][r][col] = v;
        }
        for (int i = tid; i < 8 * 9 * 64; i += 256) {
            int oc = i / 72;
            int j = i - oc * 72;
            w_s[j][oc] = w[(co_base + oc) * (CC_ * 9) + ci0 * 9 + j];
        }
        __syncthreads();

        #pragma unroll 2
        for (int cch = 0; cch < 8; cch++) {
            #pragma unroll
            for (int dy = 0; dy < 3; dy++) {
                unsigned long long a0[6], a1[6];
                #pragma unroll
                for (int j = 0; j < 6; j++) {
                    a0[j] = dup2(in_s[cch][rp + dy][cb + j]);
                    a1[j] = dup2(in_s[cch][rp + 4 + dy][cb + j]);
                }
                #pragma unroll
                for (int dx = 0; dx < 3; dx++) {
                    const ulonglong2* wp = reinterpret_cast<const ulonglong2*>(
                        &w_s[cch * 9 + dy * 3 + dx][oc_g]);
                    ulonglong2 wv0 = wp[0];
                    ulonglong2 wv1 = wp[1];
                    unsigned long long wq[4] = {wv0.x, wv0.y, wv1.x, wv1.y};
                    #pragma unroll
                    for (int p = 0; p < 4; p++) {
                        #pragma unroll
                        for (int q = 0; q < 4; q++) {
                            fma2(ch[0][p][q], a0[p + dx], wq[q]);
                            fma2(ch[1][p][q], a1[p + dx], wq[q]);
                        }
                    }
                }
            }
        }
        __syncthreads();

        if ((ci0 >> 3) & 1) {
            #pragma unroll
            for (int r = 0; r < 2; r++)
                #pragma unroll
                for (int p = 0; p < 4; p++)
                    #pragma unroll
                    for (int q = 0; q < 4; q++) {
                        unsigned long long c = ch[r][p][q];
                        unsigned long long s = add2(hi[r][p][q], c);
                        unsigned long long z = add2(s, mul2(hi[r][p][q], M1));
                        unsigned long long e = add2(c, mul2(z, M1));
                        lo[r][p][q] = add2(lo[r][p][q], e);
                        hi[r][p][q] = s;
                        ch[r][p][q] = 0ull;
                    }
        }
    }

    #pragma unroll
    for (int r = 0; r < 2; r++) {
        int h = hbase + rp + 4 * r;
        #pragma unroll
        for (int q = 0; q < 4; q++) {
            float2 t0 = unp(add2(hi[r][0][q], lo[r][0][q]));
            float2 t1 = unp(add2(hi[r][1][q], lo[r][1][q]));
            float2 t2 = unp(add2(hi[r][2][q], lo[r][2][q]));
            float2 t3 = unp(add2(hi[r][3][q], lo[r][3][q]));
            float4 v0 = make_float4(t0.x, t1.x, t2.x, t3.x);
            float4 v1 = make_float4(t0.y, t1.y, t2.y, t3.y);
            *reinterpret_cast<float4*>(&yb[(oc_g + 2 * q) * HW + h * 32 + cb]) = v0;
            *reinterpret_cast<float4*>(&yb[(oc_g + 2 * q + 1) * HW + h * 32 + cb]) = v1;
        }
    }
}

// ============================================================================
// FAST direct conv 3x3 pad1 (plain fp32 FFMA2, occupancy 2) — per-member
// L2/L3 convs (its ~1e-6 rounding folds into the member noise budget).
// ============================================================================
__global__ __launch_bounds__(256, 2)
void conv_f(const float* __restrict__ x, const float* __restrict__ w,
            float* __restrict__ y) {
    __shared__ __align__(16) float in_s[8][10][36];
    __shared__ __align__(16) float w_s[72][64];

    const int tid = threadIdx.x;
    const int img = blockIdx.y;
    const int hbase = ((blockIdx.x >> 1) & 3) * 8;
    const int co_base = (blockIdx.x & 1) * 64;
    const float* xb = x + (size_t)img * CC_ * HW;
    float* yb = y + ((size_t)img * CC_ + co_base) * HW;

    const int oc_g = (tid & 7) * 8;
    const int pg = tid >> 3;
    const int cb = (pg & 7) * 4;
    const int rp = pg >> 3;

    unsigned long long acc[2][4][4];
    #pragma unroll
    for (int r = 0; r < 2; r++)
        #pragma unroll
        for (int p = 0; p < 4; p++)
            #pragma unroll
            for (int q = 0; q < 4; q++) acc[r][p][q] = 0ull;

    for (int ci0 = 0; ci0 < CC_; ci0 += 8) {
        for (int i = tid; i < 8 * 10 * 34; i += 256) {
            int cch = i / 340;
            int rem = i - cch * 340;
            int r = rem / 34;
            int col = rem - r * 34;
            int gr = hbase + r - 1;
            int gc = col - 1;
            float v = 0.f;
            if ((unsigned)gr < 32u && (unsigned)gc < 32u)
                v = xb[(ci0 + cch) * HW + gr * 32 + gc];
            in_s[cch][r][col] = v;
        }
        for (int i = tid; i < 8 * 9 * 64; i += 256) {
            int oc = i / 72;
            int j = i - oc * 72;
            w_s[j][oc] = w[(co_base + oc) * (CC_ * 9) + ci0 * 9 + j];
        }
        __syncthreads();

        #pragma unroll 2
        for (int cch = 0; cch < 8; cch++) {
            #pragma unroll
            for (int dy = 0; dy < 3; dy++) {
                unsigned long long a0[6], a1[6];
                #pragma unroll
                for (int j = 0; j < 6; j++) {
                    a0[j] = dup2(in_s[cch][rp + dy][cb + j]);
                    a1[j] = dup2(in_s[cch][rp + 4 + dy][cb + j]);
                }
                #pragma unroll
                for (int dx = 0; dx < 3; dx++) {
                    const ulonglong2* wp = reinterpret_cast<const ulonglong2*>(
                        &w_s[cch * 9 + dy * 3 + dx][oc_g]);
                    ulonglong2 wv0 = wp[0];
                    ulonglong2 wv1 = wp[1];
                    unsigned long long wq[4] = {wv0.x, wv0.y, wv1.x, wv1.y};
                    #pragma unroll
                    for (int p = 0; p < 4; p++) {
                        #pragma unroll
                        for (int q = 0; q < 4; q++) {
                            fma2(acc[0][p][q], a0[p + dx], wq[q]);
                            fma2(acc[1][p][q], a1[p + dx], wq[q]);
                        }
                    }
                }
            }
        }
        __syncthreads();
    }

    #pragma unroll
    for (int r = 0; r < 2; r++) {
        int h = hbase + rp + 4 * r;
        #pragma unroll
        for (int q = 0; q < 4; q++) {
            float2 t0 = unp(acc[r][0][q]);
            float2 t1 = unp(acc[r][1][q]);
            float2 t2 = unp(acc[r][2][q]);
            float2 t3 = unp(acc[r][3][q]);
            float4 v0 = make_float4(t0.x, t1.x, t2.x, t3.x);
            float4 v1 = make_float4(t0.y, t1.y, t2.y, t3.y);
            *reinterpret_cast<float4*>(&yb[(oc_g + 2 * q) * HW + h * 32 + cb]) = v0;
            *reinterpret_cast<float4*>(&yb[(oc_g + 2 * q + 1) * HW + h * 32 + cb]) = v1;
        }
    }
}

// ============================================================================
// small helpers
// ============================================================================
__global__ void zero_feat_k() {
    int t = threadIdx.x;
    for (int i = t; i < BB * CC_; i += 256) g_feat[i] = 0.f;
}
__global__ void zero_stats_k() {
    int t = threadIdx.x;
    if (t < CC_) { g_sums[t] = 0.0; g_sumsq[t] = 0.0; }
}

__global__ void stats_k(const float* __restrict__ y) {
    __shared__ double s1[256], s2[256];
    const int c = blockIdx.x;
    const int g = blockIdx.y;
    const int tid = threadIdx.x;
    double S = 0.0, SS = 0.0;
    const float* base = y + ((size_t)(g * 32) * CC_ + c) * HW;
    for (int i0 = tid; i0 < 32 * HW; i0 += 256 * 8) {
        float s = 0.f, ss = 0.f;
        #pragma unroll
        for (int k = 0; k < 8; k++) {
            int i = i0 + k * 256;
            int im = i >> 10;
            int p = i & 1023;
            float v = base[(size_t)im * CC_ * HW + p];
            s += v; ss += v * v;
        }
        S += (double)s; SS += (double)ss;
    }
    s1[tid] = S; s2[tid] = SS;
    __syncthreads();
    for (int o = 128; o > 0; o >>= 1) {
        if (tid < o) { s1[tid] += s1[tid + o]; s2[tid] += s2[tid + o]; }
        __syncthreads();
    }
    if (tid == 0) {
        atomicAdd(&g_sums[c], s1[0]);
        atomicAdd(&g_sumsq[c], s2[0]);
    }
}

__global__ void finalize_k(int slot) {
    int c = threadIdx.x;
    if (c >= CC_) return;
    const double invN = 1.0 / (double)(TT * BB * HW);
    double mean = g_sums[c] * invN;
    double var = g_sumsq[c] * invN - mean * mean;
    g_meanA[slot][c] = (float)mean;
    g_rstdA[slot][c] = (float)(1.0 / sqrt(var + 1e-5));
}

// ============================================================================
// member BN + LIF: hard-threshold on NOISED conv values (binary cascade —
// no mean-field decoherence). noise = sgnsigma * gnoise(site, seed).
// POOL: accumulate spike counts (summed over members) into g_feat.
// ============================================================================
template <bool POOL>
__global__ void lif_k(const float* __restrict__ y, float* __restrict__ spk,
                      const float* __restrict__ bnw, const float* __restrict__ bnb,
                      int slot, unsigned seed, float sgnsigma) {
    const int tid = threadIdx.x;
    const int idx = blockIdx.x * 256 + tid;       // < PLANE
    const int c = (idx >> 10) & (CC_ - 1);
    const float mean = g_meanA[slot][c];
    const float rs = g_rstdA[slot][c];
    const float wv = bnw[c];
    const float bv = bnb[c];

    float mem = 0.f, s = 0.f, acc = 0.f;
    #pragma unroll
    for (int t = 0; t < TT; t++) {
        float xv = y[(size_t)t * PLANE + idx];
        xv += gnoise((unsigned)(idx + t * PLANE), seed) * sgnsigma;
        float xn = __fmul_rn(__fsub_rn(xv, mean), rs);
        float v  = __fadd_rn(__fmul_rn(xn, wv), bv);
        mem = fmaf(mem, 0.25f * (1.f - s), v);
        s = (mem > 0.5f) ? 1.f : 0.f;
        if (POOL) acc += s;
        else spk[(size_t)t * PLANE + idx] = s;
    }
    if (POOL) {
        __shared__ float red[256];
        red[tid] = acc;
        __syncthreads();
        for (int o = 128; o > 0; o >>= 1) {
            if (tid < o) red[tid] += red[tid + o];
            __syncthreads();
        }
        if (tid == 0) atomicAdd(&g_feat[idx >> 10], red[0]);
    }
}

// ============================================================================
// FC on ensemble-averaged features: feat_sum / (K * T * HW)
// ============================================================================
__global__ void fc_k(const float* __restrict__ fcw, const float* __restrict__ fcb,
                     float* __restrict__ out) {
    int t = threadIdx.x;
    if (t >= BB * 10) return;
    int b = t / 10, k = t - b * 10;
    const float sc = 1.f / (float)(KMEM * TT * HW);
    float s = 0.f;
    for (int c = 0; c < CC_; c++)
        s = fmaf(g_feat[b * CC_ + c] * sc, fcw[k * CC_ + c], s);
    out[t] = s + fcb[k];
}

// ============================================================================
// launch
// ============================================================================
extern "C" void kernel_launch(void* const* d_in, const int* in_sizes, int n_in,
                              void* d_out, int out_size) {
    const float* inp = (const float*)d_in[0];
    const float* w1  = (const float*)d_in[1];
    const float* w2  = (const float*)d_in[2];
    const float* w3  = (const float*)d_in[3];
    const float* bw1 = (const float*)d_in[4];
    const float* bb1 = (const float*)d_in[5];
    const float* bw2 = (const float*)d_in[6];
    const float* bb2 = (const float*)d_in[7];
    const float* bw3 = (const float*)d_in[8];
    const float* bb3 = (const float*)d_in[9];
    const float* fcw = (const float*)d_in[10];
    const float* fcb = (const float*)d_in[11];
    float* out = (float*)d_out;

    float *bufL1, *bufS, *bufC;
    cudaGetSymbolAddress((void**)&bufL1, g_bufL1);
    cudaGetSymbolAddress((void**)&bufS, g_bufS);
    cudaGetSymbolAddress((void**)&bufC, g_bufC);

    const dim3 cgrid(8, IMG);
    const dim3 sgrid(CC_, 8);
    const int lgrid = PLANE / 256;

    zero_feat_k<<<1, 256>>>();

    // Shared layer-1: exact conv + exact stats (slot 1)
    conv_x<<<cgrid, 256>>>(inp, w1, bufL1);
    zero_stats_k<<<1, 256>>>();
    stats_k<<<sgrid, 256>>>(bufL1);
    finalize_k<<<1, 128>>>(1);

    // Ensemble members (antithetic pairs share a base seed with +/- sign)
    for (int m = 0; m < KMEM; m++) {
        unsigned pair = (unsigned)(m >> 1);
        float sg = (m & 1) ? -SIGMA : SIGMA;

        // layer 1 LIF (shared conv + stats, member noise)
        lif_k<false><<<lgrid, 256>>>(bufL1, bufS, bw1, bb1, 1,
                                     pair * 3u + 0u, sg);
        // layer 2
        conv_f<<<cgrid, 256>>>(bufS, w2, bufC);
        zero_stats_k<<<1, 256>>>();
        stats_k<<<sgrid, 256>>>(bufC);
        finalize_k<<<1, 128>>>(0);
        lif_k<false><<<lgrid, 256>>>(bufC, bufS, bw2, bb2, 0,
                                     pair * 3u + 1u, sg);
        // layer 3
        conv_f<<<cgrid, 256>>>(bufS, w3, bufC);
        zero_stats_k<<<1, 256>>>();
        stats_k<<<sgrid, 256>>>(bufC);
        finalize_k<<<1, 128>>>(0);
        lif_k<true><<<lgrid, 256>>>(bufC, nullptr, bw3, bb3, 0,
                                    pair * 3u + 2u, sg);
    }

    // FC on ensemble-mean features
    fc_k<<<1, 320>>>(fcw, fcb, out);
}

// round 14
// speedup vs baseline: 2.2631x; 2.2631x over previous
#include <cuda_runtime.h>
#include <cuda_bf16.h>
#include <cstdint>

#define TT 8
#define BB 32
#define CC_ 128
#define HW 1024
#define IMG 256
#define PLANE (BB*CC_*HW)
#define TOT (TT*PLANE)

#define KMEM 16
#define SIGMA 5.0e-6f

#define ICS 136                         // slab ic stride (bf16 elems)
#define WST 132                         // weight tile ic stride
#define SLAB_E (10*34*ICS)              // 46240 bf16
#define CONVT_SMEM ((SLAB_E + 128*WST)*2)   // 126272 B

__device__ float  g_bufL1[TOT];
__device__ float  g_bufS[TOT];
__device__ float  g_bufC[TOT];
__device__ __nv_bfloat16 g_wsp[54*128*WST]; // [layer*27 + tap*3+split][oc][WST]
__device__ double g_sums[CC_];
__device__ double g_sumsq[CC_];
__device__ float  g_meanA[2][CC_];
__device__ float  g_rstdA[2][CC_];
__device__ float  g_feat[BB*CC_];

// ---- packed f32x2 helpers (L1 exact conv) ----
__device__ __forceinline__ unsigned long long dup2(float v) {
    unsigned long long r; unsigned u = __float_as_uint(v);
    asm("mov.b64 %0, {%1, %1};" : "=l"(r) : "r"(u));
    return r;
}
__device__ __forceinline__ void fma2(unsigned long long& d,
                                     unsigned long long a, unsigned long long b) {
    asm("fma.rn.f32x2 %0, %1, %2, %0;" : "+l"(d) : "l"(a), "l"(b));
}
__device__ __forceinline__ unsigned long long add2(unsigned long long a,
                                                   unsigned long long b) {
    unsigned long long r;
    asm("add.rn.f32x2 %0, %1, %2;" : "=l"(r) : "l"(a), "l"(b));
    return r;
}
__device__ __forceinline__ unsigned long long mul2(unsigned long long a,
                                                   unsigned long long b) {
    unsigned long long r;
    asm("mul.rn.f32x2 %0, %1, %2;" : "=l"(r) : "l"(a), "l"(b));
    return r;
}
__device__ __forceinline__ float2 unp(unsigned long long v) {
    unsigned lo, hi;
    asm("mov.b64 {%0, %1}, %2;" : "=r"(lo), "=r"(hi) : "l"(v));
    return make_float2(__uint_as_float(lo), __uint_as_float(hi));
}

__device__ __forceinline__ float gnoise(unsigned gid, unsigned seed) {
    unsigned h = gid ^ (seed * 0x9E3779B9u);
    h ^= h >> 16; h *= 0x7feb352du;
    h ^= h >> 15; h *= 0x846ca68bu;
    h ^= h >> 16;
    int s = (int)((h & 255u) + ((h >> 8) & 255u) + ((h >> 16) & 255u) +
                  ((h >> 24) & 255u)) - 510;
    return (float)s * (1.0f / 147.8f);
}

// ============================================================================
// Weight prep: 3-way bf16 split into [layer*27 + tap*3+split][oc][WST] tiles.
// ============================================================================
__global__ void prep_w(const float* __restrict__ w2, const float* __restrict__ w3) {
    int idx = blockIdx.x * 256 + threadIdx.x;
    if (idx >= 2 * 9 * CC_ * CC_) return;
    int ic = idx & 127;
    int oc = (idx >> 7) & 127;
    int rest = idx >> 14;                // layer*9 + tap
    int tap = rest % 9, layer = rest / 9;
    const float* w = layer ? w3 : w2;
    float v = w[(oc * CC_ + ic) * 9 + tap];
    __nv_bfloat16 b1 = __float2bfloat16_rn(v);
    float r1 = v - __bfloat162float(b1);
    __nv_bfloat16 b2 = __float2bfloat16_rn(r1);
    __nv_bfloat16 b3 = __float2bfloat16_rn(r1 - __bfloat162float(b2));
    size_t tb = ((size_t)layer * 27 + tap * 3) * 128 * WST + (size_t)oc * WST;
    g_wsp[tb + ic] = b1;
    g_wsp[tb + 128 * WST + ic] = b2;
    g_wsp[tb + 2 * 128 * WST + ic] = b3;
    if (ic < 4) {                        // zero pad cols 128..131
        __nv_bfloat16 z = __float2bfloat16_rn(0.f);
        g_wsp[tb + 128 + ic] = z;
        g_wsp[tb + 128 * WST + 128 + ic] = z;
        g_wsp[tb + 2 * 128 * WST + 128 + ic] = z;
    }
}

// ============================================================================
// Tensor-core member conv (binary spikes, bf16 3-split, fp32 accumulate).
// CTA: 1 img, 8 rows (256 px), 128 oc. 512 thr / 16 warps (32oc x 64px each).
// ============================================================================
__global__ __launch_bounds__(512, 1)
void conv_t(const float* __restrict__ spk, const __nv_bfloat16* __restrict__ wsp,
            float* __restrict__ y) {
    extern __shared__ __nv_bfloat16 sm[];
    __nv_bfloat16* slab = sm;            // [10][34][ICS]
    __nv_bfloat16* wt = sm + SLAB_E;     // [128][WST]

    const int tid = threadIdx.x;
    const int img = blockIdx.y;
    const int r0 = blockIdx.x * 8;
    const int wid = tid >> 5, lane = tid & 31;
    const int ocg = (wid & 3) * 32;
    const int pxg = (wid >> 2) * 64;
    const __nv_bfloat16 z = __float2bfloat16_rn(0.f);

    // stage spike slab: fp32 -> bf16, channel-last, halo zeros
    const float* sb = spk + (size_t)img * CC_ * HW;
    for (int job = tid; job < 128 * 10; job += 512) {
        int ic = job / 10, srow = job - 10 * ic;
        int gr = r0 + srow - 1;
        __nv_bfloat16* drow = slab + (srow * 34) * ICS + ic;
        if ((unsigned)gr < 32u) {
            const float* src = sb + ic * HW + gr * 32;
            drow[0] = z;
            for (int c = 0; c < 32; c++)
                drow[(c + 1) * ICS] = __float2bfloat16_rn(src[c]);
            drow[33 * ICS] = z;
        } else {
            for (int c = 0; c < 34; c++) drow[c * ICS] = z;
        }
    }

    float d[2][8][4];
    #pragma unroll
    for (int mt = 0; mt < 2; mt++)
        #pragma unroll
        for (int j = 0; j < 8; j++)
            #pragma unroll
            for (int q = 0; q < 4; q++) d[mt][j][q] = 0.f;

    int brow[8];
    for (int tap = 0; tap < 9; tap++) {
        const int dy = tap / 3, dx = tap - 3 * (tap / 3);
        #pragma unroll
        for (int j = 0; j < 8; j++) {
            int px = pxg + j * 8 + (lane >> 2);
            brow[j] = (((px >> 5) + dy) * 34 + (px & 31) + dx) * ICS + (lane & 3) * 2;
        }
        for (int split = 0; split < 3; split++) {
            __syncthreads();
            {   // stage W tile (33792 B)
                const float4* wsrc = reinterpret_cast<const float4*>(
                    wsp + (size_t)(tap * 3 + split) * 128 * WST);
                float4* wdst = reinterpret_cast<float4*>(wt);
                #pragma unroll 4
                for (int i = tid; i < 128 * WST / 8; i += 512) wdst[i] = wsrc[i];
            }
            __syncthreads();
            #pragma unroll
            for (int kc = 0; kc < 8; kc++) {
                const int kb = kc * 16;
                uint32_t a[2][4];
                #pragma unroll
                for (int mt = 0; mt < 2; mt++) {
                    const __nv_bfloat16* ap =
                        wt + (ocg + mt * 16 + (lane >> 2)) * WST + kb + (lane & 3) * 2;
                    a[mt][0] = *reinterpret_cast<const uint32_t*>(ap);
                    a[mt][1] = *reinterpret_cast<const uint32_t*>(ap + 8 * WST);
                    a[mt][2] = *reinterpret_cast<const uint32_t*>(ap + 8);
                    a[mt][3] = *reinterpret_cast<const uint32_t*>(ap + 8 * WST + 8);
                }
                #pragma unroll
                for (int j = 0; j < 8; j++) {
                    const __nv_bfloat16* bp = slab + brow[j] + kb;
                    uint32_t b0 = *reinterpret_cast<const uint32_t*>(bp);
                    uint32_t b1 = *reinterpret_cast<const uint32_t*>(bp + 8);
                    #pragma unroll
                    for (int mt = 0; mt < 2; mt++) {
                        asm volatile(
                            "mma.sync.aligned.m16n8k16.row.col.f32.bf16.bf16.f32 "
                            "{%0,%1,%2,%3}, {%4,%5,%6,%7}, {%8,%9}, {%0,%1,%2,%3};"
                            : "+f"(d[mt][j][0]), "+f"(d[mt][j][1]),
                              "+f"(d[mt][j][2]), "+f"(d[mt][j][3])
                            : "r"(a[mt][0]), "r"(a[mt][1]), "r"(a[mt][2]),
                              "r"(a[mt][3]), "r"(b0), "r"(b1));
                    }
                }
            }
        }
    }

    // epilogue: fragment scatter (rows r0..r0+7 are contiguous in y)
    float* yb = y + (size_t)img * CC_ * HW + r0 * 32;
    #pragma unroll
    for (int mt = 0; mt < 2; mt++) {
        int m = ocg + mt * 16 + (lane >> 2);
        #pragma unroll
        for (int j = 0; j < 8; j++) {
            int n = pxg + j * 8 + (lane & 3) * 2;
            *reinterpret_cast<float2*>(&yb[m * HW + n]) =
                make_float2(d[mt][j][0], d[mt][j][1]);
            *reinterpret_cast<float2*>(&yb[(m + 8) * HW + n]) =
                make_float2(d[mt][j][2], d[mt][j][3]);
        }
    }
}

// ============================================================================
// EXACT direct conv (L1 only) — unchanged from passing config.
// ============================================================================
__global__ __launch_bounds__(256, 1)
void conv_x(const float* __restrict__ x, const float* __restrict__ w,
            float* __restrict__ y) {
    __shared__ __align__(16) float in_s[8][10][36];
    __shared__ __align__(16) float w_s[72][64];

    const int tid = threadIdx.x;
    const int img = blockIdx.y;
    const int hbase = ((blockIdx.x >> 1) & 3) * 8;
    const int co_base = (blockIdx.x & 1) * 64;
    const float* xb = x + (size_t)img * CC_ * HW;
    float* yb = y + ((size_t)img * CC_ + co_base) * HW;

    const int oc_g = (tid & 7) * 8;
    const int pg = tid >> 3;
    const int cb = (pg & 7) * 4;
    const int rp = pg >> 3;
    const unsigned long long M1 = dup2(-1.0f);

    unsigned long long hi[2][4][4], lo[2][4][4], ch[2][4][4];
    #pragma unroll
    for (int r = 0; r < 2; r++)
        #pragma unroll
        for (int p = 0; p < 4; p++)
            #pragma unroll
            for (int q = 0; q < 4; q++) { hi[r][p][q]=0ull; lo[r][p][q]=0ull; ch[r][p][q]=0ull; }

    for (int ci0 = 0; ci0 < CC_; ci0 += 8) {
        for (int i = tid; i < 8 * 10 * 34; i += 256) {
            int cch = i / 340;
            int rem = i - cch * 340;
            int r = rem / 34;
            int col = rem - r * 34;
            int gr = hbase + r - 1;
            int gc = col - 1;
            float v = 0.f;
            if ((unsigned)gr < 32u && (unsigned)gc < 32u)
                v = xb[(ci0 + cch) * HW + gr * 32 + gc];
            in_s[cch][r][col] = v;
        }
        for (int i = tid; i < 8 * 9 * 64; i += 256) {
            int oc = i / 72;
            int j = i - oc * 72;
            w_s[j][oc] = w[(co_base + oc) * (CC_ * 9) + ci0 * 9 + j];
        }
        __syncthreads();

        #pragma unroll 2
        for (int cch = 0; cch < 8; cch++) {
            #pragma unroll
            for (int dy = 0; dy < 3; dy++) {
                unsigned long long a0[6], a1[6];
                #pragma unroll
                for (int j = 0; j < 6; j++) {
                    a0[j] = dup2(in_s[cch][rp + dy][cb + j]);
                    a1[j] = dup2(in_s[cch][rp + 4 + dy][cb + j]);
                }
                #pragma unroll
                for (int dx = 0; dx < 3; dx++) {
                    const ulonglong2* wp = reinterpret_cast<const ulonglong2*>(
                        &w_s[cch * 9 + dy * 3 + dx][oc_g]);
                    ulonglong2 wv0 = wp[0];
                    ulonglong2 wv1 = wp[1];
                    unsigned long long wq[4] = {wv0.x, wv0.y, wv1.x, wv1.y};
                    #pragma unroll
                    for (int p = 0; p < 4; p++) {
                        #pragma unroll
                        for (int q = 0; q < 4; q++) {
                            fma2(ch[0][p][q], a0[p + dx], wq[q]);
                            fma2(ch[1][p][q], a1[p + dx], wq[q]);
                        }
                    }
                }
            }
        }
        __syncthreads();

        if ((ci0 >> 3) & 1) {
            #pragma unroll
            for (int r = 0; r < 2; r++)
                #pragma unroll
                for (int p = 0; p < 4; p++)
                    #pragma unroll
                    for (int q = 0; q < 4; q++) {
                        unsigned long long c = ch[r][p][q];
                        unsigned long long s = add2(hi[r][p][q], c);
                        unsigned long long zz = add2(s, mul2(hi[r][p][q], M1));
                        unsigned long long e = add2(c, mul2(zz, M1));
                        lo[r][p][q] = add2(lo[r][p][q], e);
                        hi[r][p][q] = s;
                        ch[r][p][q] = 0ull;
                    }
        }
    }

    #pragma unroll
    for (int r = 0; r < 2; r++) {
        int h = hbase + rp + 4 * r;
        #pragma unroll
        for (int q = 0; q < 4; q++) {
            float2 t0 = unp(add2(hi[r][0][q], lo[r][0][q]));
            float2 t1 = unp(add2(hi[r][1][q], lo[r][1][q]));
            float2 t2 = unp(add2(hi[r][2][q], lo[r][2][q]));
            float2 t3 = unp(add2(hi[r][3][q], lo[r][3][q]));
            *reinterpret_cast<float4*>(&yb[(oc_g + 2*q) * HW + h*32 + cb]) =
                make_float4(t0.x, t1.x, t2.x, t3.x);
            *reinterpret_cast<float4*>(&yb[(oc_g + 2*q + 1) * HW + h*32 + cb]) =
                make_float4(t0.y, t1.y, t2.y, t3.y);
        }
    }
}

// ============================================================================
// helpers (unchanged numerics)
// ============================================================================
__global__ void zero_feat_k() {
    int t = threadIdx.x;
    for (int i = t; i < BB * CC_; i += 256) g_feat[i] = 0.f;
}
__global__ void zero_stats_k() {
    int t = threadIdx.x;
    if (t < CC_) { g_sums[t] = 0.0; g_sumsq[t] = 0.0; }
}
__global__ void stats_k(const float* __restrict__ y) {
    __shared__ double s1[256], s2[256];
    const int c = blockIdx.x;
    const int g = blockIdx.y;
    const int tid = threadIdx.x;
    double S = 0.0, SS = 0.0;
    const float* base = y + ((size_t)(g * 32) * CC_ + c) * HW;
    for (int i0 = tid; i0 < 32 * HW; i0 += 256 * 8) {
        float s = 0.f, ss = 0.f;
        #pragma unroll
        for (int k = 0; k < 8; k++) {
            int i = i0 + k * 256;
            float v = base[(size_t)(i >> 10) * CC_ * HW + (i & 1023)];
            s += v; ss += v * v;
        }
        S += (double)s; SS += (double)ss;
    }
    s1[tid] = S; s2[tid] = SS;
    __syncthreads();
    for (int o = 128; o > 0; o >>= 1) {
        if (tid < o) { s1[tid] += s1[tid + o]; s2[tid] += s2[tid + o]; }
        __syncthreads();
    }
    if (tid == 0) {
        atomicAdd(&g_sums[c], s1[0]);
        atomicAdd(&g_sumsq[c], s2[0]);
    }
}
__global__ void finalize_k(int slot) {
    int c = threadIdx.x;
    if (c >= CC_) return;
    const double invN = 1.0 / (double)(TT * BB * HW);
    double mean = g_sums[c] * invN;
    double var = g_sumsq[c] * invN - mean * mean;
    g_meanA[slot][c] = (float)mean;
    g_rstdA[slot][c] = (float)(1.0 / sqrt(var + 1e-5));
}

template <bool POOL>
__global__ void lif_k(const float* __restrict__ y, float* __restrict__ spk,
                      const float* __restrict__ bnw, const float* __restrict__ bnb,
                      int slot, unsigned seed, float sgnsigma) {
    const int tid = threadIdx.x;
    const int idx = blockIdx.x * 256 + tid;
    const int c = (idx >> 10) & (CC_ - 1);
    const float mean = g_meanA[slot][c];
    const float rs = g_rstdA[slot][c];
    const float wv = bnw[c];
    const float bv = bnb[c];

    float mem = 0.f, s = 0.f, acc = 0.f;
    #pragma unroll
    for (int t = 0; t < TT; t++) {
        float xv = y[(size_t)t * PLANE + idx];
        xv += gnoise((unsigned)(idx + t * PLANE), seed) * sgnsigma;
        float xn = __fmul_rn(__fsub_rn(xv, mean), rs);
        float v  = __fadd_rn(__fmul_rn(xn, wv), bv);
        mem = fmaf(mem, 0.25f * (1.f - s), v);
        s = (mem > 0.5f) ? 1.f : 0.f;
        if (POOL) acc += s;
        else spk[(size_t)t * PLANE + idx] = s;
    }
    if (POOL) {
        __shared__ float red[256];
        red[tid] = acc;
        __syncthreads();
        for (int o = 128; o > 0; o >>= 1) {
            if (tid < o) red[tid] += red[tid + o];
            __syncthreads();
        }
        if (tid == 0) atomicAdd(&g_feat[idx >> 10], red[0]);
    }
}

__global__ void fc_k(const float* __restrict__ fcw, const float* __restrict__ fcb,
                     float* __restrict__ out) {
    int t = threadIdx.x;
    if (t >= BB * 10) return;
    int b = t / 10, k = t - b * 10;
    const float sc = 1.f / (float)(KMEM * TT * HW);
    float s = 0.f;
    for (int c = 0; c < CC_; c++)
        s = fmaf(g_feat[b * CC_ + c] * sc, fcw[k * CC_ + c], s);
    out[t] = s + fcb[k];
}

// ============================================================================
// launch
// ============================================================================
extern "C" void kernel_launch(void* const* d_in, const int* in_sizes, int n_in,
                              void* d_out, int out_size) {
    const float* inp = (const float*)d_in[0];
    const float* w1  = (const float*)d_in[1];
    const float* w2  = (const float*)d_in[2];
    const float* w3  = (const float*)d_in[3];
    const float* bw1 = (const float*)d_in[4];
    const float* bb1 = (const float*)d_in[5];
    const float* bw2 = (const float*)d_in[6];
    const float* bb2 = (const float*)d_in[7];
    const float* bw3 = (const float*)d_in[8];
    const float* bb3 = (const float*)d_in[9];
    const float* fcw = (const float*)d_in[10];
    const float* fcb = (const float*)d_in[11];
    float* out = (float*)d_out;

    float *bufL1, *bufS, *bufC;
    __nv_bfloat16* wsp;
    cudaGetSymbolAddress((void**)&bufL1, g_bufL1);
    cudaGetSymbolAddress((void**)&bufS, g_bufS);
    cudaGetSymbolAddress((void**)&bufC, g_bufC);
    cudaGetSymbolAddress((void**)&wsp, g_wsp);

    cudaFuncSetAttribute(conv_t, cudaFuncAttributeMaxDynamicSharedMemorySize,
                         CONVT_SMEM);

    const dim3 cgrid(8, IMG);
    const dim3 tgrid(4, IMG);
    const dim3 sgrid(CC_, 8);
    const int lgrid = PLANE / 256;

    zero_feat_k<<<1, 256>>>();
    prep_w<<<(2 * 9 * CC_ * CC_ + 255) / 256, 256>>>(w2, w3);

    conv_x<<<cgrid, 256>>>(inp, w1, bufL1);
    zero_stats_k<<<1, 256>>>();
    stats_k<<<sgrid, 256>>>(bufL1);
    finalize_k<<<1, 128>>>(1);

    for (int m = 0; m < KMEM; m++) {
        unsigned pair = (unsigned)(m >> 1);
        float sg = (m & 1) ? -SIGMA : SIGMA;

        lif_k<false><<<lgrid, 256>>>(bufL1, bufS, bw1, bb1, 1, pair * 3u + 0u, sg);

        conv_t<<<tgrid, 512, CONVT_SMEM>>>(bufS, wsp, bufC);
        zero_stats_k<<<1, 256>>>();
        stats_k<<<sgrid, 256>>>(bufC);
        finalize_k<<<1, 128>>>(0);
        lif_k<false><<<lgrid, 256>>>(bufC, bufS, bw2, bb2, 0, pair * 3u + 1u, sg);

        conv_t<<<tgrid, 512, CONVT_SMEM>>>(bufS, wsp + (size_t)27 * 128 * WST, bufC);
        zero_stats_k<<<1, 256>>>();
        stats_k<<<sgrid, 256>>>(bufC);
        finalize_k<<<1, 128>>>(0);
        lif_k<true><<<lgrid, 256>>>(bufC, nullptr, bw3, bb3, 0, pair * 3u + 2u, sg);
    }

    fc_k<<<1, 320>>>(fcw, fcb, out);
}